// round 9
// baseline (speedup 1.0000x reference)
#include <cuda_runtime.h>
#include <cuda_fp16.h>
#include <cstdint>

#define NB      4
#define NNODES  50000
#define DIN     128
#define DOUT    64
#define NEDGES  800000
#define MTOTAL  (NB * NNODES)

#define XS_STRIDE 36
#define XS_BUF    (256 * XS_STRIDE)                 // uints per buffer
#define GEMM_SMEM (2 * XS_BUF * 4)                  // 73728 B, double buffered
#define SCAN_TILE 4096
#define NSCAN_BLOCKS ((NNODES + SCAN_TILE - 1) / SCAN_TILE)   // 13

// ---------------- device scratch ----------------
__device__ __half g_preh[MTOTAL * DOUT];          // [b][node][dout] fp16
__device__ unsigned int g_wf[16 * 8 * 32 * 2];    // W fragments, tf32, fragment order
__device__ int   g_counts[NNODES];
__device__ int   g_offs[NNODES + 1];
__device__ int   g_cursor[NNODES];
__device__ int   g_bsum[NSCAN_BLOCKS];
__device__ int2  g_edge[NEDGES];                  // {col, float_as_int(val)}

// ---------------- tf32 helpers ----------------
__device__ __forceinline__ unsigned int f2tf32(float f) {
    unsigned int u;
    asm("cvt.rna.tf32.f32 %0, %1;" : "=r"(u) : "f"(f));
    return u;
}
__device__ __forceinline__ void mma_tf32(float4& d,
                                         unsigned int a0, unsigned int a1,
                                         unsigned int a2, unsigned int a3,
                                         unsigned int b0, unsigned int b1) {
    asm("mma.sync.aligned.m16n8k8.row.col.f32.tf32.tf32.f32 "
        "{%0,%1,%2,%3}, {%4,%5,%6,%7}, {%8,%9}, {%0,%1,%2,%3};"
        : "+f"(d.x), "+f"(d.y), "+f"(d.z), "+f"(d.w)
        : "r"(a0), "r"(a1), "r"(a2), "r"(a3), "r"(b0), "r"(b1));
}

// ---------------- CSR build ----------------
__global__ void hist_kernel(const int* __restrict__ erows) {
    int base = blockIdx.x * 1024 + threadIdx.x;
    #pragma unroll
    for (int i = 0; i < 4; i++) {
        int e = base + i * 256;
        if (e < NEDGES) atomicAdd(&g_counts[erows[e]], 1);
    }
}

// phase 1: per-block local scan (4096 elems / block)
__global__ void scan1_kernel() {
    __shared__ int wsum[32];
    int tid = threadIdx.x, lane = tid & 31, wid = tid >> 5;
    int base = blockIdx.x * SCAN_TILE;

    int i0 = base + tid * 4;
    int v0 = (i0 + 0 < NNODES) ? g_counts[i0 + 0] : 0;
    int v1 = (i0 + 1 < NNODES) ? g_counts[i0 + 1] : 0;
    int v2 = (i0 + 2 < NNODES) ? g_counts[i0 + 2] : 0;
    int v3 = (i0 + 3 < NNODES) ? g_counts[i0 + 3] : 0;
    int c0 = v0, c1 = c0 + v1, c2 = c1 + v2, c3 = c2 + v3;

    int s = c3;
    #pragma unroll
    for (int off = 1; off < 32; off <<= 1) {
        int n = __shfl_up_sync(0xffffffffu, s, off);
        if (lane >= off) s += n;
    }
    if (lane == 31) wsum[wid] = s;
    __syncthreads();
    if (wid == 0) {
        int t = wsum[lane];
        #pragma unroll
        for (int off = 1; off < 32; off <<= 1) {
            int n = __shfl_up_sync(0xffffffffu, t, off);
            if (lane >= off) t += n;
        }
        wsum[lane] = t;
        if (lane == 31) g_bsum[blockIdx.x] = t;
    }
    __syncthreads();

    int excl = (wid > 0 ? wsum[wid - 1] : 0) + (s - c3);
    if (i0 + 0 < NNODES) { g_offs[i0 + 1] = excl + c0; g_cursor[i0 + 0] = excl; }
    if (i0 + 1 < NNODES) { g_offs[i0 + 2] = excl + c1; g_cursor[i0 + 1] = excl + c0; }
    if (i0 + 2 < NNODES) { g_offs[i0 + 3] = excl + c2; g_cursor[i0 + 2] = excl + c1; }
    if (i0 + 3 < NNODES) { g_offs[i0 + 4] = excl + c3; g_cursor[i0 + 3] = excl + c2; }
    if (blockIdx.x == 0 && tid == 0) g_offs[0] = 0;
}

// phase 2: one warp scans block sums (exclusive)
__global__ void scan2_kernel() {
    int lane = threadIdx.x;
    int v = (lane < NSCAN_BLOCKS) ? g_bsum[lane] : 0;
    int s = v;
    #pragma unroll
    for (int off = 1; off < 32; off <<= 1) {
        int n = __shfl_up_sync(0xffffffffu, s, off);
        if (lane >= off) s += n;
    }
    if (lane < NSCAN_BLOCKS) g_bsum[lane] = s - v;
}

// phase 3: add block offsets
__global__ void scan3_kernel() {
    int boff = g_bsum[blockIdx.x];
    if (boff == 0) return;
    int tid = threadIdx.x;
    int base = blockIdx.x * SCAN_TILE;
    #pragma unroll
    for (int q = 0; q < 4; q++) {
        int i = base + tid * 4 + q;
        if (i < NNODES) {
            g_offs[i + 1] += boff;
            g_cursor[i]   += boff;
        }
    }
}

// scatter: 4 independent edges per thread, packed 8B store
__global__ void scatter_kernel(const int* __restrict__ erows,
                               const int* __restrict__ ecols,
                               const float* __restrict__ evals) {
    int base = blockIdx.x * 1024 + threadIdx.x;
    #pragma unroll
    for (int i = 0; i < 4; i++) {
        int e = base + i * 256;
        if (e < NEDGES) {
            int r = erows[e];
            int pos = atomicAdd(&g_cursor[r], 1);
            g_edge[pos] = make_int2(ecols[e], __float_as_int(evals[e]));
        }
    }
}

// ---------------- W fragment prep ----------------
__global__ void wfrag_kernel(const float* __restrict__ w) {
    int i = blockIdx.x * 256 + threadIdx.x;   // 0..8191
    int kk = i >> 9;
    int j  = (i >> 6) & 7;
    int ln = (i >> 1) & 31;
    int rg = i & 1;
    int k  = kk * 8 + (ln & 3) + rg * 4;
    int c  = j * 8 + (ln >> 2);
    g_wf[i] = f2tf32(w[k * DOUT + c]);
}

// ---------------- GEMM: tf32 mma.sync, cp.async double-buffered staging ----------------
// block 256 thr = 8 warps; warp tile 32x64; block tile 256x64; K chunks of 32.
__global__ __launch_bounds__(256) void gemm_kernel(const float* __restrict__ x) {
    extern __shared__ float xs[];   // 2 x [256][36] fp32

    int t = threadIdx.x, lane = t & 31, wid = t >> 5;
    int g   = lane >> 2;
    int tig = lane & 3;

    size_t mblk = (size_t)blockIdx.x * 256;

    float4 acc[2][8] = {};
    const uint2* wf2 = reinterpret_cast<const uint2*>(g_wf);
    int rA = wid * 32 + g;

    // stage chunk kc into buffer b (raw fp32 via cp.async, 8 x 16B per thread)
    auto stage = [&](int kc, int b) {
        #pragma unroll
        for (int it = 0; it < 8; it++) {
            int i   = t + it * 256;
            int row = i >> 3;
            int q   = i & 7;
            size_t m = mblk + row;
            if (m >= MTOTAL) m = MTOTAL - 1;
            const float* src = x + m * DIN + kc * 32 + q * 4;
            unsigned int dst = (unsigned int)__cvta_generic_to_shared(
                &xs[b * XS_BUF + row * XS_STRIDE + q * 4]);
            asm volatile("cp.async.ca.shared.global [%0], [%1], 16;" :: "r"(dst), "l"(src));
        }
        asm volatile("cp.async.commit_group;");
    };

    stage(0, 0);

    #pragma unroll 1
    for (int kc = 0; kc < 4; kc++) {
        if (kc < 3) {
            stage(kc + 1, (kc + 1) & 1);
            asm volatile("cp.async.wait_group 1;");
        } else {
            asm volatile("cp.async.wait_group 0;");
        }
        __syncthreads();

        const float* xb = &xs[(kc & 1) * XS_BUF];

        #pragma unroll
        for (int kk8 = 0; kk8 < 4; kk8++) {
            int kkg = kc * 4 + kk8;
            int klo = kk8 * 8 + tig;

            unsigned int a00 = f2tf32(xb[(rA     ) * XS_STRIDE + klo]);
            unsigned int a01 = f2tf32(xb[(rA +  8) * XS_STRIDE + klo]);
            unsigned int a02 = f2tf32(xb[(rA     ) * XS_STRIDE + klo + 4]);
            unsigned int a03 = f2tf32(xb[(rA +  8) * XS_STRIDE + klo + 4]);
            unsigned int a10 = f2tf32(xb[(rA + 16) * XS_STRIDE + klo]);
            unsigned int a11 = f2tf32(xb[(rA + 24) * XS_STRIDE + klo]);
            unsigned int a12 = f2tf32(xb[(rA + 16) * XS_STRIDE + klo + 4]);
            unsigned int a13 = f2tf32(xb[(rA + 24) * XS_STRIDE + klo + 4]);

            #pragma unroll
            for (int j = 0; j < 8; j++) {
                uint2 b = __ldg(&wf2[(kkg * 8 + j) * 32 + lane]);
                mma_tf32(acc[0][j], a00, a01, a02, a03, b.x, b.y);
                mma_tf32(acc[1][j], a10, a11, a12, a13, b.x, b.y);
            }
        }
        __syncthreads();   // all warps done with buf (kc&1) before it is re-staged
    }

    #pragma unroll
    for (int f = 0; f < 2; f++) {
        size_t mr0 = mblk + wid * 32 + f * 16 + g;
        size_t mr1 = mr0 + 8;
        bool v0 = mr0 < MTOTAL;
        bool v1 = mr1 < MTOTAL;
        #pragma unroll
        for (int j = 0; j < 8; j++) {
            __half2 h0 = __floats2half2_rn(acc[f][j].x, acc[f][j].y);
            __half2 h1 = __floats2half2_rn(acc[f][j].z, acc[f][j].w);
            if (v0) *reinterpret_cast<__half2*>(g_preh + mr0 * DOUT + j * 8 + tig * 2) = h0;
            if (v1) *reinterpret_cast<__half2*>(g_preh + mr1 * DOUT + j * 8 + tig * 2) = h1;
        }
    }
}

// ---------------- aggregation (unchanged) ----------------
__global__ void aggregate_kernel(float* __restrict__ out) {
    int gwarp = (blockIdx.x * blockDim.x + threadIdx.x) >> 5;
    int lane  = threadIdx.x & 31;
    if (gwarp >= NNODES) return;

    int start = g_offs[gwarp];
    int end   = g_offs[gwarp + 1];

    float2 a0 = make_float2(0.f, 0.f), a1 = a0, a2 = a0, a3 = a0;
    const __half2* p2 = reinterpret_cast<const __half2*>(g_preh);
    const size_t bstride = (size_t)NNODES * (DOUT / 2);

    int i = start;
    for (; i + 1 < end; i += 2) {
        int2 e0 = g_edge[i];
        int2 e1 = g_edge[i + 1];
        float v0 = __int_as_float(e0.y);
        float v1 = __int_as_float(e1.y);
        size_t b0 = (size_t)e0.x * (DOUT / 2) + lane;
        size_t b1 = (size_t)e1.x * (DOUT / 2) + lane;
        __half2 q00 = p2[b0];
        __half2 q01 = p2[b0 +     bstride];
        __half2 q02 = p2[b0 + 2 * bstride];
        __half2 q03 = p2[b0 + 3 * bstride];
        __half2 q10 = p2[b1];
        __half2 q11 = p2[b1 +     bstride];
        __half2 q12 = p2[b1 + 2 * bstride];
        __half2 q13 = p2[b1 + 3 * bstride];
        float2 f;
        f = __half22float2(q00); a0.x += v0 * f.x; a0.y += v0 * f.y;
        f = __half22float2(q01); a1.x += v0 * f.x; a1.y += v0 * f.y;
        f = __half22float2(q02); a2.x += v0 * f.x; a2.y += v0 * f.y;
        f = __half22float2(q03); a3.x += v0 * f.x; a3.y += v0 * f.y;
        f = __half22float2(q10); a0.x += v1 * f.x; a0.y += v1 * f.y;
        f = __half22float2(q11); a1.x += v1 * f.x; a1.y += v1 * f.y;
        f = __half22float2(q12); a2.x += v1 * f.x; a2.y += v1 * f.y;
        f = __half22float2(q13); a3.x += v1 * f.x; a3.y += v1 * f.y;
    }
    if (i < end) {
        int2 e0 = g_edge[i];
        float v0 = __int_as_float(e0.y);
        size_t b0 = (size_t)e0.x * (DOUT / 2) + lane;
        float2 f;
        f = __half22float2(p2[b0]);               a0.x += v0 * f.x; a0.y += v0 * f.y;
        f = __half22float2(p2[b0 +     bstride]); a1.x += v0 * f.x; a1.y += v0 * f.y;
        f = __half22float2(p2[b0 + 2 * bstride]); a2.x += v0 * f.x; a2.y += v0 * f.y;
        f = __half22float2(p2[b0 + 3 * bstride]); a3.x += v0 * f.x; a3.y += v0 * f.y;
    }

    float2* o2 = reinterpret_cast<float2*>(out);
    size_t ob = (size_t)gwarp * (DOUT / 2) + lane;
    o2[ob]               = make_float2(fmaxf(a0.x, 0.f), fmaxf(a0.y, 0.f));
    o2[ob +     bstride] = make_float2(fmaxf(a1.x, 0.f), fmaxf(a1.y, 0.f));
    o2[ob + 2 * bstride] = make_float2(fmaxf(a2.x, 0.f), fmaxf(a2.y, 0.f));
    o2[ob + 3 * bstride] = make_float2(fmaxf(a3.x, 0.f), fmaxf(a3.y, 0.f));
}

// ---------------- launch ----------------
extern "C" void kernel_launch(void* const* d_in, const int* in_sizes, int n_in,
                              void* d_out, int out_size) {
    const float* x     = (const float*)d_in[0];
    const float* w     = (const float*)d_in[1];
    const float* evals = (const float*)d_in[2];
    const int*   erows = (const int*)  d_in[3];
    const int*   ecols = (const int*)  d_in[4];
    float* out = (float*)d_out;

    (void)in_sizes; (void)n_in; (void)out_size;

    cudaFuncSetAttribute(gemm_kernel,
                         cudaFuncAttributeMaxDynamicSharedMemorySize, GEMM_SMEM);

    void* counts_ptr = nullptr;
    cudaGetSymbolAddress(&counts_ptr, g_counts);
    cudaMemsetAsync(counts_ptr, 0, NNODES * sizeof(int), 0);

    hist_kernel<<<(NEDGES + 1023) / 1024, 256>>>(erows);             // idx 0
    wfrag_kernel<<<32, 256>>>(w);                                    // idx 1
    scan1_kernel<<<NSCAN_BLOCKS, 1024>>>();                          // idx 2
    gemm_kernel<<<(MTOTAL + 255) / 256, 256, GEMM_SMEM>>>(x);        // idx 3 <- profiled
    scan2_kernel<<<1, 32>>>();                                       // idx 4
    scan3_kernel<<<NSCAN_BLOCKS, 1024>>>();                          // idx 5
    scatter_kernel<<<(NEDGES + 1023) / 1024, 256>>>(erows, ecols, evals);
    aggregate_kernel<<<(NNODES * 32 + 255) / 256, 256>>>(out);
}

// round 10
// speedup vs baseline: 1.0463x; 1.0463x over previous
#include <cuda_runtime.h>
#include <cuda_fp16.h>
#include <cstdint>

#define NB      4
#define NNODES  50000
#define DIN     128
#define DOUT    64
#define NEDGES  800000
#define MTOTAL  (NB * NNODES)

#define XS_STRIDE 132                               // 128 + 4: bank(row*132+k) = (4row+k)%32
#define GEMM_SMEM (128 * XS_STRIDE * 4)             // 67584 B, full-K single buffer
#define SCAN_TILE 4096
#define NSCAN_BLOCKS ((NNODES + SCAN_TILE - 1) / SCAN_TILE)   // 13

// ---------------- device scratch ----------------
__device__ __half g_preh[MTOTAL * DOUT];          // [b][node][dout] fp16
__device__ unsigned int g_wf[16 * 8 * 32 * 2];    // W fragments, tf32, fragment order
__device__ int   g_counts[NNODES];
__device__ int   g_offs[NNODES + 1];
__device__ int   g_cursor[NNODES];
__device__ int   g_bsum[NSCAN_BLOCKS];
__device__ int2  g_edge[NEDGES];                  // {col, float_as_int(val)}

// ---------------- tf32 helpers ----------------
__device__ __forceinline__ unsigned int f2tf32(float f) {
    unsigned int u;
    asm("cvt.rna.tf32.f32 %0, %1;" : "=r"(u) : "f"(f));
    return u;
}
__device__ __forceinline__ void mma_tf32(float4& d,
                                         unsigned int a0, unsigned int a1,
                                         unsigned int a2, unsigned int a3,
                                         unsigned int b0, unsigned int b1) {
    asm("mma.sync.aligned.m16n8k8.row.col.f32.tf32.tf32.f32 "
        "{%0,%1,%2,%3}, {%4,%5,%6,%7}, {%8,%9}, {%0,%1,%2,%3};"
        : "+f"(d.x), "+f"(d.y), "+f"(d.z), "+f"(d.w)
        : "r"(a0), "r"(a1), "r"(a2), "r"(a3), "r"(b0), "r"(b1));
}

// ---------------- CSR build ----------------
__global__ void hist_kernel(const int* __restrict__ erows) {
    int base = blockIdx.x * 1024 + threadIdx.x;
    #pragma unroll
    for (int i = 0; i < 4; i++) {
        int e = base + i * 256;
        if (e < NEDGES) atomicAdd(&g_counts[erows[e]], 1);
    }
}

// phase 1: per-block local scan (4096 elems / block)
__global__ void scan1_kernel() {
    __shared__ int wsum[32];
    int tid = threadIdx.x, lane = tid & 31, wid = tid >> 5;
    int base = blockIdx.x * SCAN_TILE;

    int i0 = base + tid * 4;
    int v0 = (i0 + 0 < NNODES) ? g_counts[i0 + 0] : 0;
    int v1 = (i0 + 1 < NNODES) ? g_counts[i0 + 1] : 0;
    int v2 = (i0 + 2 < NNODES) ? g_counts[i0 + 2] : 0;
    int v3 = (i0 + 3 < NNODES) ? g_counts[i0 + 3] : 0;
    int c0 = v0, c1 = c0 + v1, c2 = c1 + v2, c3 = c2 + v3;

    int s = c3;
    #pragma unroll
    for (int off = 1; off < 32; off <<= 1) {
        int n = __shfl_up_sync(0xffffffffu, s, off);
        if (lane >= off) s += n;
    }
    if (lane == 31) wsum[wid] = s;
    __syncthreads();
    if (wid == 0) {
        int t = wsum[lane];
        #pragma unroll
        for (int off = 1; off < 32; off <<= 1) {
            int n = __shfl_up_sync(0xffffffffu, t, off);
            if (lane >= off) t += n;
        }
        wsum[lane] = t;
        if (lane == 31) g_bsum[blockIdx.x] = t;
    }
    __syncthreads();

    int excl = (wid > 0 ? wsum[wid - 1] : 0) + (s - c3);
    if (i0 + 0 < NNODES) { g_offs[i0 + 1] = excl + c0; g_cursor[i0 + 0] = excl; }
    if (i0 + 1 < NNODES) { g_offs[i0 + 2] = excl + c1; g_cursor[i0 + 1] = excl + c0; }
    if (i0 + 2 < NNODES) { g_offs[i0 + 3] = excl + c2; g_cursor[i0 + 2] = excl + c1; }
    if (i0 + 3 < NNODES) { g_offs[i0 + 4] = excl + c3; g_cursor[i0 + 3] = excl + c2; }
    if (blockIdx.x == 0 && tid == 0) g_offs[0] = 0;
}

// phase 2: one warp scans block sums (exclusive)
__global__ void scan2_kernel() {
    int lane = threadIdx.x;
    int v = (lane < NSCAN_BLOCKS) ? g_bsum[lane] : 0;
    int s = v;
    #pragma unroll
    for (int off = 1; off < 32; off <<= 1) {
        int n = __shfl_up_sync(0xffffffffu, s, off);
        if (lane >= off) s += n;
    }
    if (lane < NSCAN_BLOCKS) g_bsum[lane] = s - v;
}

// phase 3: add block offsets
__global__ void scan3_kernel() {
    int boff = g_bsum[blockIdx.x];
    if (boff == 0) return;
    int tid = threadIdx.x;
    int base = blockIdx.x * SCAN_TILE;
    #pragma unroll
    for (int q = 0; q < 4; q++) {
        int i = base + tid * 4 + q;
        if (i < NNODES) {
            g_offs[i + 1] += boff;
            g_cursor[i]   += boff;
        }
    }
}

// scatter: 4 independent edges per thread, packed 8B store
__global__ void scatter_kernel(const int* __restrict__ erows,
                               const int* __restrict__ ecols,
                               const float* __restrict__ evals) {
    int base = blockIdx.x * 1024 + threadIdx.x;
    #pragma unroll
    for (int i = 0; i < 4; i++) {
        int e = base + i * 256;
        if (e < NEDGES) {
            int r = erows[e];
            int pos = atomicAdd(&g_cursor[r], 1);
            g_edge[pos] = make_int2(ecols[e], __float_as_int(evals[e]));
        }
    }
}

// ---------------- W fragment prep ----------------
__global__ void wfrag_kernel(const float* __restrict__ w) {
    int i = blockIdx.x * 256 + threadIdx.x;   // 0..8191
    int kk = i >> 9;
    int j  = (i >> 6) & 7;
    int ln = (i >> 1) & 31;
    int rg = i & 1;
    int k  = kk * 8 + (ln & 3) + rg * 4;
    int c  = j * 8 + (ln >> 2);
    g_wf[i] = f2tf32(w[k * DOUT + c]);
}

// ---------------- GEMM: tf32 mma.sync, full-K single-stage ----------------
// block 256 thr = 8 warps; block tile 128(M) x 64(N), full K=128 in smem.
// warp tile 32(M) x 32(N): warps 0-3 -> cols 0-31, warps 4-7 -> cols 32-63.
__global__ __launch_bounds__(256, 3) void gemm_kernel(const float* __restrict__ x) {
    extern __shared__ float xs[];   // [128][132] fp32

    int t = threadIdx.x, lane = t & 31, wid = t >> 5;
    int g   = lane >> 2;
    int tig = lane & 3;

    size_t mblk = (size_t)blockIdx.x * 128;

    // stage full 128x128 tile: 4096 float4, 16 per thread, one burst
    #pragma unroll
    for (int it = 0; it < 16; it++) {
        int i   = t + it * 256;
        int row = i >> 5;        // 32 float4 per row
        int q   = i & 31;
        size_t m = mblk + row;
        if (m >= MTOTAL) m = MTOTAL - 1;
        const float* src = x + m * DIN + q * 4;
        unsigned int dst = (unsigned int)__cvta_generic_to_shared(
            &xs[row * XS_STRIDE + q * 4]);
        asm volatile("cp.async.ca.shared.global [%0], [%1], 16;" :: "r"(dst), "l"(src));
    }
    asm volatile("cp.async.commit_group;");
    asm volatile("cp.async.wait_group 0;");
    __syncthreads();

    int mw = (wid & 3) * 32;      // warp M offset within tile
    int nw = (wid >> 2) * 4;      // warp j base (cols nw*8 .. nw*8+31)
    int rA = mw + g;

    float4 acc[2][4] = {};
    const uint2* wf2 = reinterpret_cast<const uint2*>(g_wf);

    #pragma unroll
    for (int kk8 = 0; kk8 < 16; kk8++) {
        int klo = kk8 * 8 + tig;

        unsigned int a00 = f2tf32(xs[(rA     ) * XS_STRIDE + klo]);
        unsigned int a01 = f2tf32(xs[(rA +  8) * XS_STRIDE + klo]);
        unsigned int a02 = f2tf32(xs[(rA     ) * XS_STRIDE + klo + 4]);
        unsigned int a03 = f2tf32(xs[(rA +  8) * XS_STRIDE + klo + 4]);
        unsigned int a10 = f2tf32(xs[(rA + 16) * XS_STRIDE + klo]);
        unsigned int a11 = f2tf32(xs[(rA + 24) * XS_STRIDE + klo]);
        unsigned int a12 = f2tf32(xs[(rA + 16) * XS_STRIDE + klo + 4]);
        unsigned int a13 = f2tf32(xs[(rA + 24) * XS_STRIDE + klo + 4]);

        #pragma unroll
        for (int j = 0; j < 4; j++) {
            uint2 b = __ldg(&wf2[(kk8 * 8 + nw + j) * 32 + lane]);
            mma_tf32(acc[0][j], a00, a01, a02, a03, b.x, b.y);
            mma_tf32(acc[1][j], a10, a11, a12, a13, b.x, b.y);
        }
    }

    #pragma unroll
    for (int f = 0; f < 2; f++) {
        size_t mr0 = mblk + mw + f * 16 + g;
        size_t mr1 = mr0 + 8;
        bool v0 = mr0 < MTOTAL;
        bool v1 = mr1 < MTOTAL;
        #pragma unroll
        for (int j = 0; j < 4; j++) {
            __half2 h0 = __floats2half2_rn(acc[f][j].x, acc[f][j].y);
            __half2 h1 = __floats2half2_rn(acc[f][j].z, acc[f][j].w);
            int col = (nw + j) * 8 + tig * 2;
            if (v0) *reinterpret_cast<__half2*>(g_preh + mr0 * DOUT + col) = h0;
            if (v1) *reinterpret_cast<__half2*>(g_preh + mr1 * DOUT + col) = h1;
        }
    }
}

// ---------------- aggregation (unchanged) ----------------
__global__ void aggregate_kernel(float* __restrict__ out) {
    int gwarp = (blockIdx.x * blockDim.x + threadIdx.x) >> 5;
    int lane  = threadIdx.x & 31;
    if (gwarp >= NNODES) return;

    int start = g_offs[gwarp];
    int end   = g_offs[gwarp + 1];

    float2 a0 = make_float2(0.f, 0.f), a1 = a0, a2 = a0, a3 = a0;
    const __half2* p2 = reinterpret_cast<const __half2*>(g_preh);
    const size_t bstride = (size_t)NNODES * (DOUT / 2);

    int i = start;
    for (; i + 1 < end; i += 2) {
        int2 e0 = g_edge[i];
        int2 e1 = g_edge[i + 1];
        float v0 = __int_as_float(e0.y);
        float v1 = __int_as_float(e1.y);
        size_t b0 = (size_t)e0.x * (DOUT / 2) + lane;
        size_t b1 = (size_t)e1.x * (DOUT / 2) + lane;
        __half2 q00 = p2[b0];
        __half2 q01 = p2[b0 +     bstride];
        __half2 q02 = p2[b0 + 2 * bstride];
        __half2 q03 = p2[b0 + 3 * bstride];
        __half2 q10 = p2[b1];
        __half2 q11 = p2[b1 +     bstride];
        __half2 q12 = p2[b1 + 2 * bstride];
        __half2 q13 = p2[b1 + 3 * bstride];
        float2 f;
        f = __half22float2(q00); a0.x += v0 * f.x; a0.y += v0 * f.y;
        f = __half22float2(q01); a1.x += v0 * f.x; a1.y += v0 * f.y;
        f = __half22float2(q02); a2.x += v0 * f.x; a2.y += v0 * f.y;
        f = __half22float2(q03); a3.x += v0 * f.x; a3.y += v0 * f.y;
        f = __half22float2(q10); a0.x += v1 * f.x; a0.y += v1 * f.y;
        f = __half22float2(q11); a1.x += v1 * f.x; a1.y += v1 * f.y;
        f = __half22float2(q12); a2.x += v1 * f.x; a2.y += v1 * f.y;
        f = __half22float2(q13); a3.x += v1 * f.x; a3.y += v1 * f.y;
    }
    if (i < end) {
        int2 e0 = g_edge[i];
        float v0 = __int_as_float(e0.y);
        size_t b0 = (size_t)e0.x * (DOUT / 2) + lane;
        float2 f;
        f = __half22float2(p2[b0]);               a0.x += v0 * f.x; a0.y += v0 * f.y;
        f = __half22float2(p2[b0 +     bstride]); a1.x += v0 * f.x; a1.y += v0 * f.y;
        f = __half22float2(p2[b0 + 2 * bstride]); a2.x += v0 * f.x; a2.y += v0 * f.y;
        f = __half22float2(p2[b0 + 3 * bstride]); a3.x += v0 * f.x; a3.y += v0 * f.y;
    }

    float2* o2 = reinterpret_cast<float2*>(out);
    size_t ob = (size_t)gwarp * (DOUT / 2) + lane;
    o2[ob]               = make_float2(fmaxf(a0.x, 0.f), fmaxf(a0.y, 0.f));
    o2[ob +     bstride] = make_float2(fmaxf(a1.x, 0.f), fmaxf(a1.y, 0.f));
    o2[ob + 2 * bstride] = make_float2(fmaxf(a2.x, 0.f), fmaxf(a2.y, 0.f));
    o2[ob + 3 * bstride] = make_float2(fmaxf(a3.x, 0.f), fmaxf(a3.y, 0.f));
}

// ---------------- launch ----------------
extern "C" void kernel_launch(void* const* d_in, const int* in_sizes, int n_in,
                              void* d_out, int out_size) {
    const float* x     = (const float*)d_in[0];
    const float* w     = (const float*)d_in[1];
    const float* evals = (const float*)d_in[2];
    const int*   erows = (const int*)  d_in[3];
    const int*   ecols = (const int*)  d_in[4];
    float* out = (float*)d_out;

    (void)in_sizes; (void)n_in; (void)out_size;

    cudaFuncSetAttribute(gemm_kernel,
                         cudaFuncAttributeMaxDynamicSharedMemorySize, GEMM_SMEM);

    void* counts_ptr = nullptr;
    cudaGetSymbolAddress(&counts_ptr, g_counts);
    cudaMemsetAsync(counts_ptr, 0, NNODES * sizeof(int), 0);

    hist_kernel<<<(NEDGES + 1023) / 1024, 256>>>(erows);             // idx 0
    wfrag_kernel<<<32, 256>>>(w);                                    // idx 1
    scan1_kernel<<<NSCAN_BLOCKS, 1024>>>();                          // idx 2
    gemm_kernel<<<(MTOTAL + 127) / 128, 256, GEMM_SMEM>>>(x);        // idx 3 <- profiled
    scan2_kernel<<<1, 32>>>();                                       // idx 4
    scan3_kernel<<<NSCAN_BLOCKS, 1024>>>();                          // idx 5
    scatter_kernel<<<(NEDGES + 1023) / 1024, 256>>>(erows, ecols, evals);
    aggregate_kernel<<<(NNODES * 32 + 255) / 256, 256>>>(out);
}

// round 12
// speedup vs baseline: 1.0826x; 1.0347x over previous
#include <cuda_runtime.h>
#include <cuda_fp16.h>
#include <cstdint>

#define NB      4
#define NNODES  50000
#define DIN     128
#define DOUT    64
#define NEDGES  800000
#define MTOTAL  (NB * NNODES)

#define XS_STRIDE 132                               // 128 + 4 pad
#define GEMM_SMEM (128 * XS_STRIDE * 4)             // 67584 B
#define SCAN_TILE 4096                              // 1 << 12
#define NSCAN_BLOCKS ((NNODES + SCAN_TILE - 1) / SCAN_TILE)   // 13

// ---------------- device scratch ----------------
__device__ __half g_preh[MTOTAL * DOUT];          // [b][node][dout] fp16
__device__ unsigned int g_wf[16 * 8 * 32 * 2];    // W fragments, tf32, fragment order
__device__ int   g_counts[NNODES];
__device__ int   g_offs[NNODES + 1];              // LOCAL inclusive offsets (per scan block)
__device__ int   g_cursor[NNODES];                // LOCAL exclusive starts
__device__ int   g_bsum[NSCAN_BLOCKS];            // exclusive block sums
__device__ int2  g_edge[NEDGES];                  // {col, float_as_int(val)}

// ---------------- tf32 helpers ----------------
__device__ __forceinline__ unsigned int f2tf32(float f) {
    unsigned int u;
    asm("cvt.rna.tf32.f32 %0, %1;" : "=r"(u) : "f"(f));
    return u;
}
__device__ __forceinline__ void mma_tf32(float4& d,
                                         unsigned int a0, unsigned int a1,
                                         unsigned int a2, unsigned int a3,
                                         unsigned int b0, unsigned int b1) {
    asm("mma.sync.aligned.m16n8k8.row.col.f32.tf32.tf32.f32 "
        "{%0,%1,%2,%3}, {%4,%5,%6,%7}, {%8,%9}, {%0,%1,%2,%3};"
        : "+f"(d.x), "+f"(d.y), "+f"(d.z), "+f"(d.w)
        : "r"(a0), "r"(a1), "r"(a2), "r"(a3), "r"(b0), "r"(b1));
}

// ---------------- CSR build ----------------
__global__ void hist_kernel(const int* __restrict__ erows) {
    int base = blockIdx.x * 1024 + threadIdx.x;
    #pragma unroll
    for (int i = 0; i < 4; i++) {
        int e = base + i * 256;
        if (e < NEDGES) atomicAdd(&g_counts[erows[e]], 1);
    }
}

// phase 1: per-block local scan; offs/cursor stay block-local, bsum gets totals
__global__ void scan1_kernel() {
    __shared__ int wsum[32];
    int tid = threadIdx.x, lane = tid & 31, wid = tid >> 5;
    int base = blockIdx.x * SCAN_TILE;

    int i0 = base + tid * 4;
    int v0 = (i0 + 0 < NNODES) ? g_counts[i0 + 0] : 0;
    int v1 = (i0 + 1 < NNODES) ? g_counts[i0 + 1] : 0;
    int v2 = (i0 + 2 < NNODES) ? g_counts[i0 + 2] : 0;
    int v3 = (i0 + 3 < NNODES) ? g_counts[i0 + 3] : 0;
    int c0 = v0, c1 = c0 + v1, c2 = c1 + v2, c3 = c2 + v3;

    int s = c3;
    #pragma unroll
    for (int off = 1; off < 32; off <<= 1) {
        int n = __shfl_up_sync(0xffffffffu, s, off);
        if (lane >= off) s += n;
    }
    if (lane == 31) wsum[wid] = s;
    __syncthreads();
    if (wid == 0) {
        int t = wsum[lane];
        #pragma unroll
        for (int off = 1; off < 32; off <<= 1) {
            int n = __shfl_up_sync(0xffffffffu, t, off);
            if (lane >= off) t += n;
        }
        wsum[lane] = t;
        if (lane == 31) g_bsum[blockIdx.x] = t;
    }
    __syncthreads();

    int excl = (wid > 0 ? wsum[wid - 1] : 0) + (s - c3);
    if (i0 + 0 < NNODES) { g_offs[i0 + 1] = excl + c0; g_cursor[i0 + 0] = excl; }
    if (i0 + 1 < NNODES) { g_offs[i0 + 2] = excl + c1; g_cursor[i0 + 1] = excl + c0; }
    if (i0 + 2 < NNODES) { g_offs[i0 + 3] = excl + c2; g_cursor[i0 + 2] = excl + c1; }
    if (i0 + 3 < NNODES) { g_offs[i0 + 4] = excl + c3; g_cursor[i0 + 3] = excl + c2; }
    if (blockIdx.x == 0 && tid == 0) g_offs[0] = 0;
}

// phase 2: one warp, exclusive scan of block sums
__global__ void scan2_kernel() {
    int lane = threadIdx.x;
    int v = (lane < NSCAN_BLOCKS) ? g_bsum[lane] : 0;
    int s = v;
    #pragma unroll
    for (int off = 1; off < 32; off <<= 1) {
        int n = __shfl_up_sync(0xffffffffu, s, off);
        if (lane >= off) s += n;
    }
    if (lane < NSCAN_BLOCKS) g_bsum[lane] = s - v;
}

// scatter: local cursor + block offset (scan3 folded in)
__global__ void scatter_kernel(const int* __restrict__ erows,
                               const int* __restrict__ ecols,
                               const float* __restrict__ evals) {
    int base = blockIdx.x * 1024 + threadIdx.x;
    #pragma unroll
    for (int i = 0; i < 4; i++) {
        int e = base + i * 256;
        if (e < NEDGES) {
            int r = erows[e];
            int pos = atomicAdd(&g_cursor[r], 1) + g_bsum[r >> 12];
            g_edge[pos] = make_int2(ecols[e], __float_as_int(evals[e]));
        }
    }
}

// ---------------- W fragment prep ----------------
__global__ void wfrag_kernel(const float* __restrict__ w) {
    int i = blockIdx.x * 256 + threadIdx.x;   // 0..8191
    int kk = i >> 9;
    int j  = (i >> 6) & 7;
    int ln = (i >> 1) & 31;
    int rg = i & 1;
    int k  = kk * 8 + (ln & 3) + rg * 4;
    int c  = j * 8 + (ln >> 2);
    g_wf[i] = f2tf32(w[k * DOUT + c]);
}

// ---------------- GEMM: tf32 mma.sync, full-K single-stage (R10 form) ----------------
__global__ __launch_bounds__(256, 3) void gemm_kernel(const float* __restrict__ x) {
    extern __shared__ float xs[];   // [128][132] fp32

    int t = threadIdx.x, lane = t & 31, wid = t >> 5;
    int g   = lane >> 2;
    int tig = lane & 3;

    size_t mblk = (size_t)blockIdx.x * 128;

    #pragma unroll
    for (int it = 0; it < 16; it++) {
        int i   = t + it * 256;
        int row = i >> 5;
        int q   = i & 31;
        size_t m = mblk + row;
        if (m >= MTOTAL) m = MTOTAL - 1;
        const float* src = x + m * DIN + q * 4;
        unsigned int dst = (unsigned int)__cvta_generic_to_shared(
            &xs[row * XS_STRIDE + q * 4]);
        asm volatile("cp.async.ca.shared.global [%0], [%1], 16;" :: "r"(dst), "l"(src));
    }
    asm volatile("cp.async.commit_group;");
    asm volatile("cp.async.wait_group 0;");
    __syncthreads();

    int mw = (wid & 3) * 32;
    int nw = (wid >> 2) * 4;
    int rA = mw + g;

    float4 acc[2][4] = {};
    const uint2* wf2 = reinterpret_cast<const uint2*>(g_wf);

    #pragma unroll
    for (int kk8 = 0; kk8 < 16; kk8++) {
        int klo = kk8 * 8 + tig;

        unsigned int a00 = f2tf32(xs[(rA     ) * XS_STRIDE + klo]);
        unsigned int a01 = f2tf32(xs[(rA +  8) * XS_STRIDE + klo]);
        unsigned int a02 = f2tf32(xs[(rA     ) * XS_STRIDE + klo + 4]);
        unsigned int a03 = f2tf32(xs[(rA +  8) * XS_STRIDE + klo + 4]);
        unsigned int a10 = f2tf32(xs[(rA + 16) * XS_STRIDE + klo]);
        unsigned int a11 = f2tf32(xs[(rA + 24) * XS_STRIDE + klo]);
        unsigned int a12 = f2tf32(xs[(rA + 16) * XS_STRIDE + klo + 4]);
        unsigned int a13 = f2tf32(xs[(rA + 24) * XS_STRIDE + klo + 4]);

        #pragma unroll
        for (int j = 0; j < 4; j++) {
            uint2 b = __ldg(&wf2[(kk8 * 8 + nw + j) * 32 + lane]);
            mma_tf32(acc[0][j], a00, a01, a02, a03, b.x, b.y);
            mma_tf32(acc[1][j], a10, a11, a12, a13, b.x, b.y);
        }
    }

    #pragma unroll
    for (int f = 0; f < 2; f++) {
        size_t mr0 = mblk + mw + f * 16 + g;
        size_t mr1 = mr0 + 8;
        bool v0 = mr0 < MTOTAL;
        bool v1 = mr1 < MTOTAL;
        #pragma unroll
        for (int j = 0; j < 4; j++) {
            __half2 h0 = __floats2half2_rn(acc[f][j].x, acc[f][j].y);
            __half2 h1 = __floats2half2_rn(acc[f][j].z, acc[f][j].w);
            int col = (nw + j) * 8 + tig * 2;
            if (v0) *reinterpret_cast<__half2*>(g_preh + mr0 * DOUT + col) = h0;
            if (v1) *reinterpret_cast<__half2*>(g_preh + mr1 * DOUT + col) = h1;
        }
    }
}

// ---------------- aggregation: warp/row, 4-edge unroll, scan3 folded ----------------
__device__ __forceinline__ void acc_edge(const __half2* __restrict__ p2,
                                         size_t bstride, int lane, int2 e,
                                         float2& a0, float2& a1,
                                         float2& a2, float2& a3) {
    float v = __int_as_float(e.y);
    size_t b = (size_t)e.x * (DOUT / 2) + lane;
    float2 f;
    f = __half22float2(p2[b]);               a0.x += v * f.x; a0.y += v * f.y;
    f = __half22float2(p2[b +     bstride]); a1.x += v * f.x; a1.y += v * f.y;
    f = __half22float2(p2[b + 2 * bstride]); a2.x += v * f.x; a2.y += v * f.y;
    f = __half22float2(p2[b + 3 * bstride]); a3.x += v * f.x; a3.y += v * f.y;
}

__global__ void aggregate_kernel(float* __restrict__ out) {
    int gwarp = (blockIdx.x * blockDim.x + threadIdx.x) >> 5;
    int lane  = threadIdx.x & 31;
    if (gwarp >= NNODES) return;

    // reconstruct global offsets from local scan + block sums
    int sbPrev = (gwarp > 0) ? ((gwarp - 1) >> 12) : 0;
    int start = g_offs[gwarp]     + g_bsum[sbPrev];
    int end   = g_offs[gwarp + 1] + g_bsum[gwarp >> 12];

    float2 a0 = make_float2(0.f, 0.f), a1 = a0, a2 = a0, a3 = a0;
    const __half2* p2 = reinterpret_cast<const __half2*>(g_preh);
    const size_t bstride = (size_t)NNODES * (DOUT / 2);

    int i = start;
    for (; i + 3 < end; i += 4) {
        int2 e0 = g_edge[i];
        int2 e1 = g_edge[i + 1];
        int2 e2 = g_edge[i + 2];
        int2 e3 = g_edge[i + 3];
        acc_edge(p2, bstride, lane, e0, a0, a1, a2, a3);
        acc_edge(p2, bstride, lane, e1, a0, a1, a2, a3);
        acc_edge(p2, bstride, lane, e2, a0, a1, a2, a3);
        acc_edge(p2, bstride, lane, e3, a0, a1, a2, a3);
    }
    for (; i < end; i++) {
        int2 e0 = g_edge[i];
        acc_edge(p2, bstride, lane, e0, a0, a1, a2, a3);
    }

    float2* o2 = reinterpret_cast<float2*>(out);
    size_t ob = (size_t)gwarp * (DOUT / 2) + lane;
    o2[ob]               = make_float2(fmaxf(a0.x, 0.f), fmaxf(a0.y, 0.f));
    o2[ob +     bstride] = make_float2(fmaxf(a1.x, 0.f), fmaxf(a1.y, 0.f));
    o2[ob + 2 * bstride] = make_float2(fmaxf(a2.x, 0.f), fmaxf(a2.y, 0.f));
    o2[ob + 3 * bstride] = make_float2(fmaxf(a3.x, 0.f), fmaxf(a3.y, 0.f));
}

// ---------------- launch (serial, stream-free) ----------------
extern "C" void kernel_launch(void* const* d_in, const int* in_sizes, int n_in,
                              void* d_out, int out_size) {
    const float* x     = (const float*)d_in[0];
    const float* w     = (const float*)d_in[1];
    const float* evals = (const float*)d_in[2];
    const int*   erows = (const int*)  d_in[3];
    const int*   ecols = (const int*)  d_in[4];
    float* out = (float*)d_out;

    (void)in_sizes; (void)n_in; (void)out_size;

    cudaFuncSetAttribute(gemm_kernel,
                         cudaFuncAttributeMaxDynamicSharedMemorySize, GEMM_SMEM);

    void* counts_ptr = nullptr;
    cudaGetSymbolAddress(&counts_ptr, g_counts);
    cudaMemsetAsync(counts_ptr, 0, NNODES * sizeof(int), 0);

    hist_kernel<<<(NEDGES + 1023) / 1024, 256>>>(erows);             // idx 0
    wfrag_kernel<<<32, 256>>>(w);                                    // idx 1
    scan1_kernel<<<NSCAN_BLOCKS, 1024>>>();                          // idx 2
    gemm_kernel<<<(MTOTAL + 127) / 128, 256, GEMM_SMEM>>>(x);        // idx 3 <- profiled
    scan2_kernel<<<1, 32>>>();                                       // idx 4
    scatter_kernel<<<(NEDGES + 1023) / 1024, 256>>>(erows, ecols, evals);
    aggregate_kernel<<<(NNODES * 32 + 255) / 256, 256>>>(out);
}

// round 13
// speedup vs baseline: 1.1015x; 1.0175x over previous
#include <cuda_runtime.h>
#include <cuda_fp16.h>
#include <cstdint>

#define NB      4
#define NNODES  50000
#define DIN     128
#define DOUT    64
#define NEDGES  800000
#define MTOTAL  (NB * NNODES)

#define XS_STRIDE 132                               // 128 + 4 pad
#define GEMM_SMEM (128 * XS_STRIDE * 4)             // 67584 B
#define SCAN_TILE 4096                              // 1 << 12
#define NSCAN_BLOCKS ((NNODES + SCAN_TILE - 1) / SCAN_TILE)   // 13

// ---------------- device scratch ----------------
__device__ __half g_preh[MTOTAL * DOUT];          // [b][node][dout] fp16
__device__ unsigned int g_wf[16 * 8 * 32 * 2];    // W fragments, tf32, PAIRED order
__device__ int   g_counts[NNODES];
__device__ int   g_offs[NNODES + 1];              // local inclusive offsets
__device__ int   g_cursor[NNODES];                // local exclusive starts
__device__ int   g_bsum[NSCAN_BLOCKS];            // exclusive block sums
__device__ int2  g_edge[NEDGES];                  // {col, float_as_int(val)}

// ---------------- tf32 helpers ----------------
__device__ __forceinline__ unsigned int f2tf32(float f) {
    unsigned int u;
    asm("cvt.rna.tf32.f32 %0, %1;" : "=r"(u) : "f"(f));
    return u;
}
__device__ __forceinline__ void mma_tf32(float4& d,
                                         unsigned int a0, unsigned int a1,
                                         unsigned int a2, unsigned int a3,
                                         unsigned int b0, unsigned int b1) {
    asm("mma.sync.aligned.m16n8k8.row.col.f32.tf32.tf32.f32 "
        "{%0,%1,%2,%3}, {%4,%5,%6,%7}, {%8,%9}, {%0,%1,%2,%3};"
        : "+f"(d.x), "+f"(d.y), "+f"(d.z), "+f"(d.w)
        : "r"(a0), "r"(a1), "r"(a2), "r"(a3), "r"(b0), "r"(b1));
}

// ---------------- CSR build ----------------
// hist: 8 edges/thread, int4 loads, 8 independent atomic chains
__global__ void hist_kernel(const int* __restrict__ erows) {
    int e0 = (blockIdx.x * 256 + threadIdx.x) * 8;
    if (e0 + 7 < NEDGES) {
        int4 r0 = *reinterpret_cast<const int4*>(erows + e0);
        int4 r1 = *reinterpret_cast<const int4*>(erows + e0 + 4);
        atomicAdd(&g_counts[r0.x], 1);
        atomicAdd(&g_counts[r0.y], 1);
        atomicAdd(&g_counts[r0.z], 1);
        atomicAdd(&g_counts[r0.w], 1);
        atomicAdd(&g_counts[r1.x], 1);
        atomicAdd(&g_counts[r1.y], 1);
        atomicAdd(&g_counts[r1.z], 1);
        atomicAdd(&g_counts[r1.w], 1);
    } else {
        for (int e = e0; e < NEDGES; e++) atomicAdd(&g_counts[erows[e]], 1);
    }
}

// phase 1: per-block local scan; offs/cursor block-local, bsum totals
__global__ void scan1_kernel() {
    __shared__ int wsum[32];
    int tid = threadIdx.x, lane = tid & 31, wid = tid >> 5;
    int base = blockIdx.x * SCAN_TILE;

    int i0 = base + tid * 4;
    int v0 = (i0 + 0 < NNODES) ? g_counts[i0 + 0] : 0;
    int v1 = (i0 + 1 < NNODES) ? g_counts[i0 + 1] : 0;
    int v2 = (i0 + 2 < NNODES) ? g_counts[i0 + 2] : 0;
    int v3 = (i0 + 3 < NNODES) ? g_counts[i0 + 3] : 0;
    int c0 = v0, c1 = c0 + v1, c2 = c1 + v2, c3 = c2 + v3;

    int s = c3;
    #pragma unroll
    for (int off = 1; off < 32; off <<= 1) {
        int n = __shfl_up_sync(0xffffffffu, s, off);
        if (lane >= off) s += n;
    }
    if (lane == 31) wsum[wid] = s;
    __syncthreads();
    if (wid == 0) {
        int t = wsum[lane];
        #pragma unroll
        for (int off = 1; off < 32; off <<= 1) {
            int n = __shfl_up_sync(0xffffffffu, t, off);
            if (lane >= off) t += n;
        }
        wsum[lane] = t;
        if (lane == 31) g_bsum[blockIdx.x] = t;
    }
    __syncthreads();

    int excl = (wid > 0 ? wsum[wid - 1] : 0) + (s - c3);
    if (i0 + 0 < NNODES) { g_offs[i0 + 1] = excl + c0; g_cursor[i0 + 0] = excl; }
    if (i0 + 1 < NNODES) { g_offs[i0 + 2] = excl + c1; g_cursor[i0 + 1] = excl + c0; }
    if (i0 + 2 < NNODES) { g_offs[i0 + 3] = excl + c2; g_cursor[i0 + 2] = excl + c1; }
    if (i0 + 3 < NNODES) { g_offs[i0 + 4] = excl + c3; g_cursor[i0 + 3] = excl + c2; }
    if (blockIdx.x == 0 && tid == 0) g_offs[0] = 0;
}

// phase 2: one warp, exclusive scan of block sums
__global__ void scan2_kernel() {
    int lane = threadIdx.x;
    int v = (lane < NSCAN_BLOCKS) ? g_bsum[lane] : 0;
    int s = v;
    #pragma unroll
    for (int off = 1; off < 32; off <<= 1) {
        int n = __shfl_up_sync(0xffffffffu, s, off);
        if (lane >= off) s += n;
    }
    if (lane < NSCAN_BLOCKS) g_bsum[lane] = s - v;
}

// scatter: 8 edges/thread, vectorized loads, scan3 folded in
__device__ __forceinline__ void scat1(int r, int c, float v) {
    int pos = atomicAdd(&g_cursor[r], 1) + g_bsum[r >> 12];
    g_edge[pos] = make_int2(c, __float_as_int(v));
}

__global__ void scatter_kernel(const int* __restrict__ erows,
                               const int* __restrict__ ecols,
                               const float* __restrict__ evals) {
    int e0 = (blockIdx.x * 256 + threadIdx.x) * 8;
    if (e0 + 7 < NEDGES) {
        int4   r0 = *reinterpret_cast<const int4*>(erows + e0);
        int4   r1 = *reinterpret_cast<const int4*>(erows + e0 + 4);
        int4   c0 = *reinterpret_cast<const int4*>(ecols + e0);
        int4   c1 = *reinterpret_cast<const int4*>(ecols + e0 + 4);
        float4 v0 = *reinterpret_cast<const float4*>(evals + e0);
        float4 v1 = *reinterpret_cast<const float4*>(evals + e0 + 4);
        scat1(r0.x, c0.x, v0.x);
        scat1(r0.y, c0.y, v0.y);
        scat1(r0.z, c0.z, v0.z);
        scat1(r0.w, c0.w, v0.w);
        scat1(r1.x, c1.x, v1.x);
        scat1(r1.y, c1.y, v1.y);
        scat1(r1.z, c1.z, v1.z);
        scat1(r1.w, c1.w, v1.w);
    } else {
        for (int e = e0; e < NEDGES; e++) scat1(erows[e], ecols[e], evals[e]);
    }
}

// ---------------- W fragment prep: PAIRED layout ----------------
// i = ((kk8*4 + jpg)*32 + ln)*4 + q ; j = jpg*2 + (q>>1), reg = q&1
__global__ void wfrag_kernel(const float* __restrict__ w) {
    int i = blockIdx.x * 256 + threadIdx.x;   // 0..8191
    int q   = i & 3;
    int ln  = (i >> 2) & 31;
    int jpg = (i >> 7) & 3;
    int kk8 = i >> 9;
    int j   = jpg * 2 + (q >> 1);
    int rg  = q & 1;
    int k   = kk8 * 8 + (ln & 3) + rg * 4;
    int c   = j * 8 + (ln >> 2);
    g_wf[i] = f2tf32(w[k * DOUT + c]);
}

// ---------------- GEMM: tf32 mma.sync, paired B loads ----------------
__global__ __launch_bounds__(256, 3) void gemm_kernel(const float* __restrict__ x) {
    extern __shared__ float xs[];   // [128][132] fp32

    int t = threadIdx.x, lane = t & 31, wid = t >> 5;
    int g   = lane >> 2;
    int tig = lane & 3;

    size_t mblk = (size_t)blockIdx.x * 128;

    #pragma unroll
    for (int it = 0; it < 16; it++) {
        int i   = t + it * 256;
        int row = i >> 5;
        int q   = i & 31;
        size_t m = mblk + row;
        if (m >= MTOTAL) m = MTOTAL - 1;
        const float* src = x + m * DIN + q * 4;
        unsigned int dst = (unsigned int)__cvta_generic_to_shared(
            &xs[row * XS_STRIDE + q * 4]);
        asm volatile("cp.async.ca.shared.global [%0], [%1], 16;" :: "r"(dst), "l"(src));
    }
    asm volatile("cp.async.commit_group;");
    asm volatile("cp.async.wait_group 0;");
    __syncthreads();

    int mw  = (wid & 3) * 32;
    int nw  = (wid >> 2) * 4;     // j base
    int nwp = (wid >> 2) * 2;     // j-pair base
    int rA  = mw + g;

    float4 acc[2][4] = {};
    const uint4* wf4 = reinterpret_cast<const uint4*>(g_wf);

    #pragma unroll
    for (int kk8 = 0; kk8 < 16; kk8++) {
        int klo = kk8 * 8 + tig;

        unsigned int a00 = f2tf32(xs[(rA     ) * XS_STRIDE + klo]);
        unsigned int a01 = f2tf32(xs[(rA +  8) * XS_STRIDE + klo]);
        unsigned int a02 = f2tf32(xs[(rA     ) * XS_STRIDE + klo + 4]);
        unsigned int a03 = f2tf32(xs[(rA +  8) * XS_STRIDE + klo + 4]);
        unsigned int a10 = f2tf32(xs[(rA + 16) * XS_STRIDE + klo]);
        unsigned int a11 = f2tf32(xs[(rA + 24) * XS_STRIDE + klo]);
        unsigned int a12 = f2tf32(xs[(rA + 16) * XS_STRIDE + klo + 4]);
        unsigned int a13 = f2tf32(xs[(rA + 24) * XS_STRIDE + klo + 4]);

        #pragma unroll
        for (int jp = 0; jp < 2; jp++) {
            uint4 bb = __ldg(&wf4[(kk8 * 4 + nwp + jp) * 32 + lane]);
            mma_tf32(acc[0][jp * 2],     a00, a01, a02, a03, bb.x, bb.y);
            mma_tf32(acc[1][jp * 2],     a10, a11, a12, a13, bb.x, bb.y);
            mma_tf32(acc[0][jp * 2 + 1], a00, a01, a02, a03, bb.z, bb.w);
            mma_tf32(acc[1][jp * 2 + 1], a10, a11, a12, a13, bb.z, bb.w);
        }
    }

    #pragma unroll
    for (int f = 0; f < 2; f++) {
        size_t mr0 = mblk + mw + f * 16 + g;
        size_t mr1 = mr0 + 8;
        bool v0 = mr0 < MTOTAL;
        bool v1 = mr1 < MTOTAL;
        #pragma unroll
        for (int j = 0; j < 4; j++) {
            __half2 h0 = __floats2half2_rn(acc[f][j].x, acc[f][j].y);
            __half2 h1 = __floats2half2_rn(acc[f][j].z, acc[f][j].w);
            int col = (nw + j) * 8 + tig * 2;
            if (v0) *reinterpret_cast<__half2*>(g_preh + mr0 * DOUT + col) = h0;
            if (v1) *reinterpret_cast<__half2*>(g_preh + mr1 * DOUT + col) = h1;
        }
    }
}

// ---------------- aggregation: warp/row, 4-edge unroll (R12 form) ----------------
__device__ __forceinline__ void acc_edge(const __half2* __restrict__ p2,
                                         size_t bstride, int lane, int2 e,
                                         float2& a0, float2& a1,
                                         float2& a2, float2& a3) {
    float v = __int_as_float(e.y);
    size_t b = (size_t)e.x * (DOUT / 2) + lane;
    float2 f;
    f = __half22float2(p2[b]);               a0.x += v * f.x; a0.y += v * f.y;
    f = __half22float2(p2[b +     bstride]); a1.x += v * f.x; a1.y += v * f.y;
    f = __half22float2(p2[b + 2 * bstride]); a2.x += v * f.x; a2.y += v * f.y;
    f = __half22float2(p2[b + 3 * bstride]); a3.x += v * f.x; a3.y += v * f.y;
}

__global__ void aggregate_kernel(float* __restrict__ out) {
    int gwarp = (blockIdx.x * blockDim.x + threadIdx.x) >> 5;
    int lane  = threadIdx.x & 31;
    if (gwarp >= NNODES) return;

    int sbPrev = (gwarp > 0) ? ((gwarp - 1) >> 12) : 0;
    int start = g_offs[gwarp]     + g_bsum[sbPrev];
    int end   = g_offs[gwarp + 1] + g_bsum[gwarp >> 12];

    float2 a0 = make_float2(0.f, 0.f), a1 = a0, a2 = a0, a3 = a0;
    const __half2* p2 = reinterpret_cast<const __half2*>(g_preh);
    const size_t bstride = (size_t)NNODES * (DOUT / 2);

    int i = start;
    for (; i + 3 < end; i += 4) {
        int2 e0 = g_edge[i];
        int2 e1 = g_edge[i + 1];
        int2 e2 = g_edge[i + 2];
        int2 e3 = g_edge[i + 3];
        acc_edge(p2, bstride, lane, e0, a0, a1, a2, a3);
        acc_edge(p2, bstride, lane, e1, a0, a1, a2, a3);
        acc_edge(p2, bstride, lane, e2, a0, a1, a2, a3);
        acc_edge(p2, bstride, lane, e3, a0, a1, a2, a3);
    }
    for (; i < end; i++) {
        int2 e0 = g_edge[i];
        acc_edge(p2, bstride, lane, e0, a0, a1, a2, a3);
    }

    float2* o2 = reinterpret_cast<float2*>(out);
    size_t ob = (size_t)gwarp * (DOUT / 2) + lane;
    o2[ob]               = make_float2(fmaxf(a0.x, 0.f), fmaxf(a0.y, 0.f));
    o2[ob +     bstride] = make_float2(fmaxf(a1.x, 0.f), fmaxf(a1.y, 0.f));
    o2[ob + 2 * bstride] = make_float2(fmaxf(a2.x, 0.f), fmaxf(a2.y, 0.f));
    o2[ob + 3 * bstride] = make_float2(fmaxf(a3.x, 0.f), fmaxf(a3.y, 0.f));
}

// ---------------- launch ----------------
extern "C" void kernel_launch(void* const* d_in, const int* in_sizes, int n_in,
                              void* d_out, int out_size) {
    const float* x     = (const float*)d_in[0];
    const float* w     = (const float*)d_in[1];
    const float* evals = (const float*)d_in[2];
    const int*   erows = (const int*)  d_in[3];
    const int*   ecols = (const int*)  d_in[4];
    float* out = (float*)d_out;

    (void)in_sizes; (void)n_in; (void)out_size;

    cudaFuncSetAttribute(gemm_kernel,
                         cudaFuncAttributeMaxDynamicSharedMemorySize, GEMM_SMEM);

    void* counts_ptr = nullptr;
    cudaGetSymbolAddress(&counts_ptr, g_counts);
    cudaMemsetAsync(counts_ptr, 0, NNODES * sizeof(int), 0);

    hist_kernel<<<(NEDGES / 8 + 255) / 256, 256>>>(erows);           // idx 0
    wfrag_kernel<<<32, 256>>>(w);                                    // idx 1
    scan1_kernel<<<NSCAN_BLOCKS, 1024>>>();                          // idx 2
    gemm_kernel<<<(MTOTAL + 127) / 128, 256, GEMM_SMEM>>>(x);        // idx 3 <- profiled
    scan2_kernel<<<1, 32>>>();                                       // idx 4
    scatter_kernel<<<(NEDGES / 8 + 255) / 256, 256>>>(erows, ecols, evals);
    aggregate_kernel<<<(NNODES * 32 + 255) / 256, 256>>>(out);
}

// round 15
// speedup vs baseline: 1.2773x; 1.1596x over previous
#include <cuda_runtime.h>
#include <cuda_fp16.h>
#include <cstdint>

#define NB      4
#define NNODES  50000
#define DIN     128
#define DOUT    64
#define NEDGES  800000
#define MTOTAL  (NB * NNODES)

#define XH_STRIDE 136                               // halves per row; conflict-free frags
#define GEMM_SMEM (128 * XH_STRIDE * 2)             // 34816 B
#define SCAN_TILE 4096                              // 1 << 12
#define NSCAN_BLOCKS ((NNODES + SCAN_TILE - 1) / SCAN_TILE)   // 13

// ---------------- device scratch ----------------
__device__ __half g_preh[MTOTAL * DOUT];          // [b][node][dout] fp16
__device__ unsigned int g_wfh[8 * 4 * 32 * 4];    // W fp16 fragments: [kk16][jpg][lane][4]
__device__ int   g_counts[NNODES];
__device__ int   g_offs[NNODES + 1];              // local inclusive offsets
__device__ int   g_cursor[NNODES];                // local exclusive starts
__device__ int   g_bsum[NSCAN_BLOCKS];            // exclusive block sums
__device__ int2  g_edge[NEDGES];                  // {col, float_as_int(val)}

// ---------------- mma helper: m16n8k16 fp16 in, fp32 accum ----------------
__device__ __forceinline__ void mma_f16(float4& d,
                                        unsigned int a0, unsigned int a1,
                                        unsigned int a2, unsigned int a3,
                                        unsigned int b0, unsigned int b1) {
    asm("mma.sync.aligned.m16n8k16.row.col.f32.f16.f16.f32 "
        "{%0,%1,%2,%3}, {%4,%5,%6,%7}, {%8,%9}, {%0,%1,%2,%3};"
        : "+f"(d.x), "+f"(d.y), "+f"(d.z), "+f"(d.w)
        : "r"(a0), "r"(a1), "r"(a2), "r"(a3), "r"(b0), "r"(b1));
}
__device__ __forceinline__ unsigned int h2u(__half2 h) {
    return *reinterpret_cast<unsigned int*>(&h);
}

// ---------------- CSR build ----------------
__global__ void hist_kernel(const int* __restrict__ erows) {
    int e0 = (blockIdx.x * 256 + threadIdx.x) * 8;
    if (e0 + 7 < NEDGES) {
        int4 r0 = *reinterpret_cast<const int4*>(erows + e0);
        int4 r1 = *reinterpret_cast<const int4*>(erows + e0 + 4);
        atomicAdd(&g_counts[r0.x], 1);
        atomicAdd(&g_counts[r0.y], 1);
        atomicAdd(&g_counts[r0.z], 1);
        atomicAdd(&g_counts[r0.w], 1);
        atomicAdd(&g_counts[r1.x], 1);
        atomicAdd(&g_counts[r1.y], 1);
        atomicAdd(&g_counts[r1.z], 1);
        atomicAdd(&g_counts[r1.w], 1);
    } else {
        for (int e = e0; e < NEDGES; e++) atomicAdd(&g_counts[erows[e]], 1);
    }
}

__global__ void scan1_kernel() {
    __shared__ int wsum[32];
    int tid = threadIdx.x, lane = tid & 31, wid = tid >> 5;
    int base = blockIdx.x * SCAN_TILE;

    int i0 = base + tid * 4;
    int v0 = (i0 + 0 < NNODES) ? g_counts[i0 + 0] : 0;
    int v1 = (i0 + 1 < NNODES) ? g_counts[i0 + 1] : 0;
    int v2 = (i0 + 2 < NNODES) ? g_counts[i0 + 2] : 0;
    int v3 = (i0 + 3 < NNODES) ? g_counts[i0 + 3] : 0;
    int c0 = v0, c1 = c0 + v1, c2 = c1 + v2, c3 = c2 + v3;

    int s = c3;
    #pragma unroll
    for (int off = 1; off < 32; off <<= 1) {
        int n = __shfl_up_sync(0xffffffffu, s, off);
        if (lane >= off) s += n;
    }
    if (lane == 31) wsum[wid] = s;
    __syncthreads();
    if (wid == 0) {
        int t = wsum[lane];
        #pragma unroll
        for (int off = 1; off < 32; off <<= 1) {
            int n = __shfl_up_sync(0xffffffffu, t, off);
            if (lane >= off) t += n;
        }
        wsum[lane] = t;
        if (lane == 31) g_bsum[blockIdx.x] = t;
    }
    __syncthreads();

    int excl = (wid > 0 ? wsum[wid - 1] : 0) + (s - c3);
    if (i0 + 0 < NNODES) { g_offs[i0 + 1] = excl + c0; g_cursor[i0 + 0] = excl; }
    if (i0 + 1 < NNODES) { g_offs[i0 + 2] = excl + c1; g_cursor[i0 + 1] = excl + c0; }
    if (i0 + 2 < NNODES) { g_offs[i0 + 3] = excl + c2; g_cursor[i0 + 2] = excl + c1; }
    if (i0 + 3 < NNODES) { g_offs[i0 + 4] = excl + c3; g_cursor[i0 + 3] = excl + c2; }
    if (blockIdx.x == 0 && tid == 0) g_offs[0] = 0;
}

__global__ void scan2_kernel() {
    int lane = threadIdx.x;
    int v = (lane < NSCAN_BLOCKS) ? g_bsum[lane] : 0;
    int s = v;
    #pragma unroll
    for (int off = 1; off < 32; off <<= 1) {
        int n = __shfl_up_sync(0xffffffffu, s, off);
        if (lane >= off) s += n;
    }
    if (lane < NSCAN_BLOCKS) g_bsum[lane] = s - v;
}

__device__ __forceinline__ void scat1(int r, int c, float v) {
    int pos = atomicAdd(&g_cursor[r], 1) + g_bsum[r >> 12];
    g_edge[pos] = make_int2(c, __float_as_int(v));
}

__global__ void scatter_kernel(const int* __restrict__ erows,
                               const int* __restrict__ ecols,
                               const float* __restrict__ evals) {
    int e0 = (blockIdx.x * 256 + threadIdx.x) * 8;
    if (e0 + 7 < NEDGES) {
        int4   r0 = *reinterpret_cast<const int4*>(erows + e0);
        int4   r1 = *reinterpret_cast<const int4*>(erows + e0 + 4);
        int4   c0 = *reinterpret_cast<const int4*>(ecols + e0);
        int4   c1 = *reinterpret_cast<const int4*>(ecols + e0 + 4);
        float4 v0 = *reinterpret_cast<const float4*>(evals + e0);
        float4 v1 = *reinterpret_cast<const float4*>(evals + e0 + 4);
        scat1(r0.x, c0.x, v0.x);
        scat1(r0.y, c0.y, v0.y);
        scat1(r0.z, c0.z, v0.z);
        scat1(r0.w, c0.w, v0.w);
        scat1(r1.x, c1.x, v1.x);
        scat1(r1.y, c1.y, v1.y);
        scat1(r1.z, c1.z, v1.z);
        scat1(r1.w, c1.w, v1.w);
    } else {
        for (int e = e0; e < NEDGES; e++) scat1(erows[e], ecols[e], evals[e]);
    }
}

// ---------------- W fragment prep: fp16, m16n8k16 B layout, paired j ----------------
// uint index i = ((kk16*4 + jpg)*32 + ln)*4 + q
// j = jpg*2 + (q>>1), breg = q&1; g = ln>>2, tig = ln&3
// b_breg = half2{ W[k0][c], W[k0+1][c] }, k0 = 2*tig + 8*breg, c = j*8 + g
__global__ void wfrag_kernel(const float* __restrict__ w) {
    int i = blockIdx.x * 256 + threadIdx.x;   // 0..4095
    int q    = i & 3;
    int ln   = (i >> 2) & 31;
    int jpg  = (i >> 7) & 3;
    int kk16 = i >> 9;
    int j    = jpg * 2 + (q >> 1);
    int br   = q & 1;
    int g    = ln >> 2;
    int tig  = ln & 3;
    int k0   = kk16 * 16 + tig * 2 + br * 8;
    int c    = j * 8 + g;
    g_wfh[i] = h2u(__floats2half2_rn(w[k0 * DOUT + c], w[(k0 + 1) * DOUT + c]));
}

// ---------------- GEMM: fp16 m16n8k16, fp32 accum ----------------
// block 256 thr = 8 warps; block tile 128(M) x 64(N), full K=128 fp16 in smem.
// warp tile 32(M) x 32(N): warps 0-3 cols 0-31, warps 4-7 cols 32-63.
__global__ __launch_bounds__(256, 4) void gemm_kernel(const float* __restrict__ x) {
    extern __shared__ __half xs[];   // [128][136] fp16

    int t = threadIdx.x, lane = t & 31, wid = t >> 5;
    int g   = lane >> 2;
    int tig = lane & 3;

    size_t mblk = (size_t)blockIdx.x * 128;

    // stage 128 rows x 128 k as fp16: 16 float4 loads per thread
    #pragma unroll
    for (int it = 0; it < 16; it++) {
        int i   = t + it * 256;
        int row = i >> 5;
        int q   = i & 31;
        size_t m = mblk + row;
        if (m >= MTOTAL) m = MTOTAL - 1;
        float4 v = *reinterpret_cast<const float4*>(x + m * DIN + q * 4);
        uint2 h;
        h.x = h2u(__floats2half2_rn(v.x, v.y));
        h.y = h2u(__floats2half2_rn(v.z, v.w));
        *reinterpret_cast<uint2*>(&xs[row * XH_STRIDE + q * 4]) = h;
    }
    __syncthreads();

    int mw  = (wid & 3) * 32;
    int nw  = (wid >> 2) * 4;     // j base (0 or 4)
    int nwp = (wid >> 2) * 2;     // j-pair base (0 or 2)
    int rA  = mw + g;

    float4 acc[2][4] = {};
    const uint4* wf4 = reinterpret_cast<const uint4*>(g_wfh);

    #pragma unroll
    for (int kk16 = 0; kk16 < 8; kk16++) {
        int klo = kk16 * 16 + tig * 2;

        unsigned int a00 = *reinterpret_cast<const unsigned int*>(&xs[(rA     ) * XH_STRIDE + klo]);
        unsigned int a01 = *reinterpret_cast<const unsigned int*>(&xs[(rA +  8) * XH_STRIDE + klo]);
        unsigned int a02 = *reinterpret_cast<const unsigned int*>(&xs[(rA     ) * XH_STRIDE + klo + 8]);
        unsigned int a03 = *reinterpret_cast<const unsigned int*>(&xs[(rA +  8) * XH_STRIDE + klo + 8]);
        unsigned int a10 = *reinterpret_cast<const unsigned int*>(&xs[(rA + 16) * XH_STRIDE + klo]);
        unsigned int a11 = *reinterpret_cast<const unsigned int*>(&xs[(rA + 24) * XH_STRIDE + klo]);
        unsigned int a12 = *reinterpret_cast<const unsigned int*>(&xs[(rA + 16) * XH_STRIDE + klo + 8]);
        unsigned int a13 = *reinterpret_cast<const unsigned int*>(&xs[(rA + 24) * XH_STRIDE + klo + 8]);

        #pragma unroll
        for (int jp = 0; jp < 2; jp++) {
            uint4 bb = __ldg(&wf4[(kk16 * 4 + nwp + jp) * 32 + lane]);
            mma_f16(acc[0][jp * 2],     a00, a01, a02, a03, bb.x, bb.y);
            mma_f16(acc[1][jp * 2],     a10, a11, a12, a13, bb.x, bb.y);
            mma_f16(acc[0][jp * 2 + 1], a00, a01, a02, a03, bb.z, bb.w);
            mma_f16(acc[1][jp * 2 + 1], a10, a11, a12, a13, bb.z, bb.w);
        }
    }

    #pragma unroll
    for (int f = 0; f < 2; f++) {
        size_t mr0 = mblk + mw + f * 16 + g;
        size_t mr1 = mr0 + 8;
        bool v0 = mr0 < MTOTAL;
        bool v1 = mr1 < MTOTAL;
        #pragma unroll
        for (int j = 0; j < 4; j++) {
            __half2 h0 = __floats2half2_rn(acc[f][j].x, acc[f][j].y);
            __half2 h1 = __floats2half2_rn(acc[f][j].z, acc[f][j].w);
            int col = (nw + j) * 8 + tig * 2;
            if (v0) *reinterpret_cast<__half2*>(g_preh + mr0 * DOUT + col) = h0;
            if (v1) *reinterpret_cast<__half2*>(g_preh + mr1 * DOUT + col) = h1;
        }
    }
}

// ---------------- aggregation: warp/row, 4-edge unroll (R13 form) ----------------
__device__ __forceinline__ void acc_edge(const __half2* __restrict__ p2,
                                         size_t bstride, int lane, int2 e,
                                         float2& a0, float2& a1,
                                         float2& a2, float2& a3) {
    float v = __int_as_float(e.y);
    size_t b = (size_t)e.x * (DOUT / 2) + lane;
    float2 f;
    f = __half22float2(p2[b]);               a0.x += v * f.x; a0.y += v * f.y;
    f = __half22float2(p2[b +     bstride]); a1.x += v * f.x; a1.y += v * f.y;
    f = __half22float2(p2[b + 2 * bstride]); a2.x += v * f.x; a2.y += v * f.y;
    f = __half22float2(p2[b + 3 * bstride]); a3.x += v * f.x; a3.y += v * f.y;
}

__global__ void aggregate_kernel(float* __restrict__ out) {
    int gwarp = (blockIdx.x * blockDim.x + threadIdx.x) >> 5;
    int lane  = threadIdx.x & 31;
    if (gwarp >= NNODES) return;

    int sbPrev = (gwarp > 0) ? ((gwarp - 1) >> 12) : 0;
    int start = g_offs[gwarp]     + g_bsum[sbPrev];
    int end   = g_offs[gwarp + 1] + g_bsum[gwarp >> 12];

    float2 a0 = make_float2(0.f, 0.f), a1 = a0, a2 = a0, a3 = a0;
    const __half2* p2 = reinterpret_cast<const __half2*>(g_preh);
    const size_t bstride = (size_t)NNODES * (DOUT / 2);

    int i = start;
    for (; i + 3 < end; i += 4) {
        int2 e0 = g_edge[i];
        int2 e1 = g_edge[i + 1];
        int2 e2 = g_edge[i + 2];
        int2 e3 = g_edge[i + 3];
        acc_edge(p2, bstride, lane, e0, a0, a1, a2, a3);
        acc_edge(p2, bstride, lane, e1, a0, a1, a2, a3);
        acc_edge(p2, bstride, lane, e2, a0, a1, a2, a3);
        acc_edge(p2, bstride, lane, e3, a0, a1, a2, a3);
    }
    for (; i < end; i++) {
        int2 e0 = g_edge[i];
        acc_edge(p2, bstride, lane, e0, a0, a1, a2, a3);
    }

    float2* o2 = reinterpret_cast<float2*>(out);
    size_t ob = (size_t)gwarp * (DOUT / 2) + lane;
    o2[ob]               = make_float2(fmaxf(a0.x, 0.f), fmaxf(a0.y, 0.f));
    o2[ob +     bstride] = make_float2(fmaxf(a1.x, 0.f), fmaxf(a1.y, 0.f));
    o2[ob + 2 * bstride] = make_float2(fmaxf(a2.x, 0.f), fmaxf(a2.y, 0.f));
    o2[ob + 3 * bstride] = make_float2(fmaxf(a3.x, 0.f), fmaxf(a3.y, 0.f));
}

// ---------------- launch ----------------
extern "C" void kernel_launch(void* const* d_in, const int* in_sizes, int n_in,
                              void* d_out, int out_size) {
    const float* x     = (const float*)d_in[0];
    const float* w     = (const float*)d_in[1];
    const float* evals = (const float*)d_in[2];
    const int*   erows = (const int*)  d_in[3];
    const int*   ecols = (const int*)  d_in[4];
    float* out = (float*)d_out;

    (void)in_sizes; (void)n_in; (void)out_size;

    cudaFuncSetAttribute(gemm_kernel,
                         cudaFuncAttributeMaxDynamicSharedMemorySize, GEMM_SMEM);

    void* counts_ptr = nullptr;
    cudaGetSymbolAddress(&counts_ptr, g_counts);
    cudaMemsetAsync(counts_ptr, 0, NNODES * sizeof(int), 0);

    hist_kernel<<<(NEDGES / 8 + 255) / 256, 256>>>(erows);           // idx 0
    wfrag_kernel<<<16, 256>>>(w);                                    // idx 1
    scan1_kernel<<<NSCAN_BLOCKS, 1024>>>();                          // idx 2
    gemm_kernel<<<(MTOTAL + 127) / 128, 256, GEMM_SMEM>>>(x);        // idx 3 <- profiled
    scan2_kernel<<<1, 32>>>();                                       // idx 4
    scatter_kernel<<<(NEDGES / 8 + 255) / 256, 256>>>(erows, ecols, evals);
    aggregate_kernel<<<(NNODES * 32 + 255) / 256, 256>>>(out);
}